// round 14
// baseline (speedup 1.0000x reference)
#include <cuda_runtime.h>
#include <cuda_bf16.h>
#include <cstdint>

// Problem constants
#define Bv    2
#define Nv    2048
#define DIMv  2048
#define Hv    16
#define KVHv  4
#define HDv   128
#define NREPv 4

// Intermediate device buffers (no dynamic allocation allowed)
__device__ float g_Q[(size_t)Bv * Nv * Hv * HDv];    // [4096, 2048]
__device__ float g_K[(size_t)Bv * Nv * KVHv * HDv];  // [4096, 512]
__device__ float g_V[(size_t)Bv * Nv * KVHv * HDv];
__device__ float g_O[(size_t)Bv * Nv * Hv * HDv];    // attention out pre-Wo (tf32-rounded)

// TF32-rounded operand copies
__device__ float g_xr[(size_t)Bv * Nv * DIMv];       // 8M
__device__ float g_Wqr[(size_t)DIMv * Hv * HDv];     // 4M
__device__ float g_Wkr[(size_t)DIMv * KVHv * HDv];   // 1M
__device__ float g_Wvr[(size_t)DIMv * KVHv * HDv];   // 1M
__device__ float g_Wor[(size_t)Hv * HDv * DIMv];     // 4M

__device__ __forceinline__ float f2tf32(float x) {
    float r;
    asm("cvt.rna.tf32.f32 %0, %1;" : "=f"(r) : "f"(x));
    return r;
}

// ---------------------------------------------------------------------------
// Round fp32 -> tf32-representable fp32 (vectorized, bandwidth-bound)
// ---------------------------------------------------------------------------
__global__ void round_tf32_kernel(const float4* __restrict__ src,
                                  float4* __restrict__ dst, int n4)
{
    int i = blockIdx.x * blockDim.x + threadIdx.x;
    if (i < n4) {
        float4 v = src[i];
        v.x = f2tf32(v.x); v.y = f2tf32(v.y);
        v.z = f2tf32(v.z); v.w = f2tf32(v.w);
        dst[i] = v;
    }
}

// ---------------------------------------------------------------------------
// TF32 tensor-core GEMM: C[M,N] = A[M,K] @ B[K,N], row-major fp32 (operands
// pre-rounded to tf32). 128x128 tile, BK=32, 256 threads = 2x4 warps of
// 64x32 warp tiles, mma.sync.m16n8k8, cp.async double buffering.
// smem strides 36 (A) / 136 (B) floats -> conflict-free fragment LDS.
// ---------------------------------------------------------------------------
#define GA_STRIDE 36
#define GB_STRIDE 136
#define GA_FLOATS (128 * GA_STRIDE)   // 4608
#define GB_FLOATS (32 * GB_STRIDE)    // 4352
#define GEMM_SMEM_BYTES ((2 * GA_FLOATS + 2 * GB_FLOATS) * 4)  // 71680

#define CP_ASYNC_CG(dst, src) \
    asm volatile("cp.async.cg.shared.global [%0], [%1], 16;" :: "r"(dst), "l"(src))
#define CP_COMMIT() asm volatile("cp.async.commit_group;")
#define CP_WAIT1()  asm volatile("cp.async.wait_group 1;")

__device__ __forceinline__ void mma_tf32(float* c, const uint32_t* a, const uint32_t* b)
{
    asm volatile(
        "mma.sync.aligned.m16n8k8.row.col.f32.tf32.tf32.f32 "
        "{%0,%1,%2,%3}, {%4,%5,%6,%7}, {%8,%9}, {%0,%1,%2,%3};"
        : "+f"(c[0]), "+f"(c[1]), "+f"(c[2]), "+f"(c[3])
        : "r"(a[0]), "r"(a[1]), "r"(a[2]), "r"(a[3]), "r"(b[0]), "r"(b[1]));
}

__global__ __launch_bounds__(256, 2) void gemm_tf32_kernel(
    const float* __restrict__ A, const float* __restrict__ B,
    float* __restrict__ C, int M, int N, int K)
{
    extern __shared__ float smem[];
    float* sA = smem;                       // [2][128][36]
    float* sB = smem + 2 * GA_FLOATS;       // [2][32][136]

    const int tid = threadIdx.x;
    const int wid = tid >> 5, lane = tid & 31;
    const int wm = wid >> 2, wn = wid & 3;
    const int lr = lane >> 2, lc = lane & 3;
    const int bx = blockIdx.x, by = blockIdx.y;

    const uint32_t sA_u = (uint32_t)__cvta_generic_to_shared(sA);
    const uint32_t sB_u = (uint32_t)__cvta_generic_to_shared(sB);

    float acc[4][4][4];
    #pragma unroll
    for (int mi = 0; mi < 4; mi++)
        #pragma unroll
        for (int ni = 0; ni < 4; ni++)
            #pragma unroll
            for (int r = 0; r < 4; r++) acc[mi][ni][r] = 0.f;

    const int nstage = K / 32;

    // stage loader
    auto load_stage = [&](int p, int st) {
        const int k0 = st * 32;
        const float* Ag = A + (size_t)(by * 128) * K + k0;
        #pragma unroll
        for (int i = 0; i < 4; i++) {
            int idx = tid + i * 256;            // 0..1023 float4s
            int r = idx >> 3, c = (idx & 7) * 4;
            uint32_t d = sA_u + (uint32_t)((p * GA_FLOATS + r * GA_STRIDE + c) * 4);
            CP_ASYNC_CG(d, Ag + (size_t)r * K + c);
        }
        const float* Bg = B + (size_t)k0 * N + bx * 128;
        #pragma unroll
        for (int i = 0; i < 4; i++) {
            int idx = tid + i * 256;
            int kr = idx >> 5, c = (idx & 31) * 4;
            uint32_t d = sB_u + (uint32_t)((p * GB_FLOATS + kr * GB_STRIDE + c) * 4);
            CP_ASYNC_CG(d, Bg + (size_t)kr * N + c);
        }
    };

    load_stage(0, 0);
    CP_COMMIT();

    for (int st = 0; st < nstage; st++) {
        if (st + 1 < nstage) load_stage((st + 1) & 1, st + 1);
        CP_COMMIT();
        CP_WAIT1();            // current stage resident
        __syncthreads();

        const float* cA = sA + (st & 1) * GA_FLOATS;
        const float* cB = sB + (st & 1) * GB_FLOATS;

        #pragma unroll
        for (int kc = 0; kc < 4; kc++) {
            const int k0 = kc * 8;
            uint32_t a[4][4];
            #pragma unroll
            for (int mi = 0; mi < 4; mi++) {
                int row0 = wm * 64 + mi * 16 + lr;
                a[mi][0] = __float_as_uint(cA[row0 * GA_STRIDE + k0 + lc]);
                a[mi][1] = __float_as_uint(cA[(row0 + 8) * GA_STRIDE + k0 + lc]);
                a[mi][2] = __float_as_uint(cA[row0 * GA_STRIDE + k0 + lc + 4]);
                a[mi][3] = __float_as_uint(cA[(row0 + 8) * GA_STRIDE + k0 + lc + 4]);
            }
            uint32_t b[4][2];
            #pragma unroll
            for (int ni = 0; ni < 4; ni++) {
                int col = wn * 32 + ni * 8 + lr;
                b[ni][0] = __float_as_uint(cB[(k0 + lc) * GB_STRIDE + col]);
                b[ni][1] = __float_as_uint(cB[(k0 + lc + 4) * GB_STRIDE + col]);
            }
            #pragma unroll
            for (int mi = 0; mi < 4; mi++)
                #pragma unroll
                for (int ni = 0; ni < 4; ni++)
                    mma_tf32(acc[mi][ni], a[mi], b[ni]);
        }
        __syncthreads();
    }

    // Epilogue
    #pragma unroll
    for (int mi = 0; mi < 4; mi++) {
        #pragma unroll
        for (int ni = 0; ni < 4; ni++) {
            int row = by * 128 + wm * 64 + mi * 16 + lr;
            int col = bx * 128 + wn * 32 + ni * 8 + lc * 2;
            float2 v0 = make_float2(acc[mi][ni][0], acc[mi][ni][1]);
            float2 v1 = make_float2(acc[mi][ni][2], acc[mi][ni][3]);
            *(float2*)(C + (size_t)row * N + col) = v0;
            *(float2*)(C + (size_t)(row + 8) * N + col) = v1;
        }
    }
}

// ---------------------------------------------------------------------------
// Flash attention (fp32, causal, GQA) — unchanged from R2 except the epilogue
// rounds O to tf32 so the Wo GEMM operand is already rounded.
// ---------------------------------------------------------------------------
#define FA_SQT  (128 * 68)
#define FA_SKT  (128 * 68)
#define FA_SV   (64 * 128)
#define FA_SP   (64 * 68)
#define FA_SMEM_FLOATS (FA_SQT + FA_SKT + FA_SV + FA_SP)

__global__ __launch_bounds__(256) void flash_kernel(
    const float* __restrict__ Q, const float* __restrict__ K,
    const float* __restrict__ V, float* __restrict__ O)
{
    extern __shared__ float smem[];
    float* sQt = smem;
    float* sKt = sQt + FA_SQT;
    float* sV  = sKt + FA_SKT;
    float* sP  = sV + FA_SV;

    const int qt = blockIdx.x, h = blockIdx.y, b = blockIdx.z;
    const int kvh = h / NREPv;
    const int tid = threadIdx.x;
    const int tx = tid & 15, ty = tid >> 4;

    {
        int r = tid >> 2, c0 = (tid & 3) * 32;
        const float* qp = Q + ((size_t)(b * Nv + qt * 64 + r) * Hv + h) * HDv + c0;
        #pragma unroll
        for (int i = 0; i < 8; i++) {
            float4 v = *(const float4*)(qp + i * 4);
            int d = c0 + i * 4;
            sQt[(d + 0) * 68 + r] = v.x;
            sQt[(d + 1) * 68 + r] = v.y;
            sQt[(d + 2) * 68 + r] = v.z;
            sQt[(d + 3) * 68 + r] = v.w;
        }
    }

    float mrow[4], lrow[4], o[4][8];
    #pragma unroll
    for (int i = 0; i < 4; i++) {
        mrow[i] = -1e30f; lrow[i] = 0.f;
        #pragma unroll
        for (int c = 0; c < 8; c++) o[i][c] = 0.f;
    }

    const float scale = 0.08838834764831845f;

    for (int kt = 0; kt <= qt; kt++) {
        {
            int r = tid >> 2, c0 = (tid & 3) * 32;
            const float* kp = K + ((size_t)(b * Nv + kt * 64 + r) * KVHv + kvh) * HDv + c0;
            const float* vp = V + ((size_t)(b * Nv + kt * 64 + r) * KVHv + kvh) * HDv + c0;
            #pragma unroll
            for (int i = 0; i < 8; i++) {
                float4 kv = *(const float4*)(kp + i * 4);
                int d = c0 + i * 4;
                sKt[(d + 0) * 68 + r] = kv.x;
                sKt[(d + 1) * 68 + r] = kv.y;
                sKt[(d + 2) * 68 + r] = kv.z;
                sKt[(d + 3) * 68 + r] = kv.w;
                *(float4*)&sV[r * 128 + d] = *(const float4*)(vp + i * 4);
            }
        }
        __syncthreads();

        float s[4][4];
        #pragma unroll
        for (int i = 0; i < 4; i++)
            #pragma unroll
            for (int j = 0; j < 4; j++) s[i][j] = 0.f;

        #pragma unroll 4
        for (int d = 0; d < 128; d++) {
            float a[4], bb[4];
            *(float4*)a  = *(const float4*)&sQt[d * 68 + ty * 4];
            *(float4*)bb = *(const float4*)&sKt[d * 68 + tx * 4];
            #pragma unroll
            for (int i = 0; i < 4; i++)
                #pragma unroll
                for (int j = 0; j < 4; j++)
                    s[i][j] += a[i] * bb[j];
        }

        const bool diag = (kt == qt);
        #pragma unroll
        for (int i = 0; i < 4; i++)
            #pragma unroll
            for (int j = 0; j < 4; j++) {
                float val = s[i][j] * scale;
                if (diag && (tx * 4 + j) > (ty * 4 + i)) val = -1e30f;
                s[i][j] = val;
            }

        #pragma unroll
        for (int i = 0; i < 4; i++) {
            float mt = fmaxf(fmaxf(s[i][0], s[i][1]), fmaxf(s[i][2], s[i][3]));
            #pragma unroll
            for (int off = 8; off >= 1; off >>= 1)
                mt = fmaxf(mt, __shfl_xor_sync(0xffffffffu, mt, off));
            float mnew  = fmaxf(mrow[i], mt);
            float alpha = __expf(mrow[i] - mnew);
            float rs = 0.f;
            #pragma unroll
            for (int j = 0; j < 4; j++) {
                float p = __expf(s[i][j] - mnew);
                s[i][j] = p; rs += p;
            }
            #pragma unroll
            for (int off = 8; off >= 1; off >>= 1)
                rs += __shfl_xor_sync(0xffffffffu, rs, off);
            lrow[i] = lrow[i] * alpha + rs;
            mrow[i] = mnew;
            #pragma unroll
            for (int c = 0; c < 8; c++) o[i][c] *= alpha;
            float4 pv = make_float4(s[i][0], s[i][1], s[i][2], s[i][3]);
            *(float4*)&sP[(ty * 4 + i) * 68 + tx * 4] = pv;
        }
        __syncthreads();

        #pragma unroll 4
        for (int j = 0; j < 64; j++) {
            float a0 = sP[(ty * 4 + 0) * 68 + j];
            float a1 = sP[(ty * 4 + 1) * 68 + j];
            float a2 = sP[(ty * 4 + 2) * 68 + j];
            float a3 = sP[(ty * 4 + 3) * 68 + j];
            float bb[8];
            *(float4*)&bb[0] = *(const float4*)&sV[j * 128 + tx * 4];
            *(float4*)&bb[4] = *(const float4*)&sV[j * 128 + 64 + tx * 4];
            #pragma unroll
            for (int c = 0; c < 8; c++) {
                o[0][c] += a0 * bb[c];
                o[1][c] += a1 * bb[c];
                o[2][c] += a2 * bb[c];
                o[3][c] += a3 * bb[c];
            }
        }
        __syncthreads();
    }

    #pragma unroll
    for (int i = 0; i < 4; i++) {
        float inv = 1.f / lrow[i];
        int row = qt * 64 + ty * 4 + i;
        float* op = O + ((size_t)(b * Nv + row) * Hv + h) * HDv;
        float4 v0 = make_float4(f2tf32(o[i][0] * inv), f2tf32(o[i][1] * inv),
                                f2tf32(o[i][2] * inv), f2tf32(o[i][3] * inv));
        float4 v1 = make_float4(f2tf32(o[i][4] * inv), f2tf32(o[i][5] * inv),
                                f2tf32(o[i][6] * inv), f2tf32(o[i][7] * inv));
        *(float4*)(op + tx * 4)      = v0;
        *(float4*)(op + 64 + tx * 4) = v1;
    }
}

// ---------------------------------------------------------------------------
// Launch
// ---------------------------------------------------------------------------
extern "C" void kernel_launch(void* const* d_in, const int* in_sizes, int n_in,
                              void* d_out, int out_size)
{
    const float* x  = (const float*)d_in[0];
    const float* Wq = (const float*)d_in[2];
    const float* Wk = (const float*)d_in[3];
    const float* Wv = (const float*)d_in[4];
    const float* Wo = (const float*)d_in[5];
    float* out = (float*)d_out;

    float *qb, *kb, *vb, *ob, *xr, *wqr, *wkr, *wvr, *wor;
    cudaGetSymbolAddress((void**)&qb, g_Q);
    cudaGetSymbolAddress((void**)&kb, g_K);
    cudaGetSymbolAddress((void**)&vb, g_V);
    cudaGetSymbolAddress((void**)&ob, g_O);
    cudaGetSymbolAddress((void**)&xr, g_xr);
    cudaGetSymbolAddress((void**)&wqr, g_Wqr);
    cudaGetSymbolAddress((void**)&wkr, g_Wkr);
    cudaGetSymbolAddress((void**)&wvr, g_Wvr);
    cudaGetSymbolAddress((void**)&wor, g_Wor);

    const int M = Bv * Nv;  // 4096
    dim3 blk(256);

    // Round operands to tf32-representable fp32
    auto roundn = [&](const float* s, float* d, size_t n) {
        int n4 = (int)(n / 4);
        round_tf32_kernel<<<(n4 + 255) / 256, 256>>>((const float4*)s, (float4*)d, n4);
    };
    roundn(x,  xr,  (size_t)M * DIMv);
    roundn(Wq, wqr, (size_t)DIMv * Hv * HDv);
    roundn(Wk, wkr, (size_t)DIMv * KVHv * HDv);
    roundn(Wv, wvr, (size_t)DIMv * KVHv * HDv);
    roundn(Wo, wor, (size_t)Hv * HDv * DIMv);

    cudaFuncSetAttribute(gemm_tf32_kernel, cudaFuncAttributeMaxDynamicSharedMemorySize,
                         GEMM_SMEM_BYTES);

    // Projections (tensor cores)
    gemm_tf32_kernel<<<dim3((Hv * HDv) / 128, M / 128), blk, GEMM_SMEM_BYTES>>>(
        xr, wqr, qb, M, Hv * HDv, DIMv);
    gemm_tf32_kernel<<<dim3((KVHv * HDv) / 128, M / 128), blk, GEMM_SMEM_BYTES>>>(
        xr, wkr, kb, M, KVHv * HDv, DIMv);
    gemm_tf32_kernel<<<dim3((KVHv * HDv) / 128, M / 128), blk, GEMM_SMEM_BYTES>>>(
        xr, wvr, vb, M, KVHv * HDv, DIMv);

    // Attention (fp32)
    const size_t fa_smem = (size_t)FA_SMEM_FLOATS * sizeof(float);
    cudaFuncSetAttribute(flash_kernel, cudaFuncAttributeMaxDynamicSharedMemorySize,
                         (int)fa_smem);
    flash_kernel<<<dim3(Nv / 64, Hv, Bv), blk, fa_smem>>>(qb, kb, vb, ob);

    // Output projection (tensor cores)
    gemm_tf32_kernel<<<dim3(DIMv / 128, M / 128), blk, GEMM_SMEM_BYTES>>>(
        ob, wor, out, M, DIMv, DIMv);
}

// round 15
// speedup vs baseline: 1.0007x; 1.0007x over previous
#include <cuda_runtime.h>
#include <cuda_bf16.h>
#include <cstdint>

// Problem constants
#define Bv    2
#define Nv    2048
#define DIMv  2048
#define Hv    16
#define KVHv  4
#define HDv   128
#define NREPv 4

// Intermediate device buffers (no dynamic allocation allowed)
__device__ float g_Q[(size_t)Bv * Nv * Hv * HDv];    // [4096, 2048]
__device__ float g_K[(size_t)Bv * Nv * KVHv * HDv];  // [4096, 512]
__device__ float g_V[(size_t)Bv * Nv * KVHv * HDv];
__device__ float g_O[(size_t)Bv * Nv * Hv * HDv];    // attention out pre-Wo (tf32-rounded)

// TF32-rounded operand copies
__device__ float g_xr[(size_t)Bv * Nv * DIMv];       // 8M
__device__ float g_Wqr[(size_t)DIMv * Hv * HDv];     // 4M
__device__ float g_Wkr[(size_t)DIMv * KVHv * HDv];   // 1M
__device__ float g_Wvr[(size_t)DIMv * KVHv * HDv];   // 1M
__device__ float g_Wor[(size_t)Hv * HDv * DIMv];     // 4M

__device__ __forceinline__ float f2tf32(float x) {
    float r;
    asm("cvt.rna.tf32.f32 %0, %1;" : "=f"(r) : "f"(x));
    return r;
}

// ---------------------------------------------------------------------------
// Round fp32 -> tf32-representable fp32 (vectorized, bandwidth-bound)
// ---------------------------------------------------------------------------
__global__ void round_tf32_kernel(const float4* __restrict__ src,
                                  float4* __restrict__ dst, int n4)
{
    int i = blockIdx.x * blockDim.x + threadIdx.x;
    if (i < n4) {
        float4 v = src[i];
        v.x = f2tf32(v.x); v.y = f2tf32(v.y);
        v.z = f2tf32(v.z); v.w = f2tf32(v.w);
        dst[i] = v;
    }
}

// ---------------------------------------------------------------------------
// TF32 tensor-core GEMM: C[M,N] = A[M,K] @ B[K,N], row-major fp32 (operands
// pre-rounded to tf32). 128x128 tile, BK=32, 256 threads = 2x4 warps of
// 64x32 warp tiles, mma.sync.m16n8k8, cp.async double buffering.
// smem strides 36 (A) / 136 (B) floats -> conflict-free fragment LDS.
// ---------------------------------------------------------------------------
#define GA_STRIDE 36
#define GB_STRIDE 136
#define GA_FLOATS (128 * GA_STRIDE)   // 4608
#define GB_FLOATS (32 * GB_STRIDE)    // 4352
#define GEMM_SMEM_BYTES ((2 * GA_FLOATS + 2 * GB_FLOATS) * 4)  // 71680

#define CP_ASYNC_CG(dst, src) \
    asm volatile("cp.async.cg.shared.global [%0], [%1], 16;" :: "r"(dst), "l"(src))
#define CP_COMMIT() asm volatile("cp.async.commit_group;")
#define CP_WAIT1()  asm volatile("cp.async.wait_group 1;")

__device__ __forceinline__ void mma_tf32(float* c, const uint32_t* a, const uint32_t* b)
{
    asm volatile(
        "mma.sync.aligned.m16n8k8.row.col.f32.tf32.tf32.f32 "
        "{%0,%1,%2,%3}, {%4,%5,%6,%7}, {%8,%9}, {%0,%1,%2,%3};"
        : "+f"(c[0]), "+f"(c[1]), "+f"(c[2]), "+f"(c[3])
        : "r"(a[0]), "r"(a[1]), "r"(a[2]), "r"(a[3]), "r"(b[0]), "r"(b[1]));
}

__global__ __launch_bounds__(256, 2) void gemm_tf32_kernel(
    const float* __restrict__ A, const float* __restrict__ B,
    float* __restrict__ C, int M, int N, int K)
{
    extern __shared__ float smem[];
    float* sA = smem;                       // [2][128][36]
    float* sB = smem + 2 * GA_FLOATS;       // [2][32][136]

    const int tid = threadIdx.x;
    const int wid = tid >> 5, lane = tid & 31;
    const int wm = wid >> 2, wn = wid & 3;
    const int lr = lane >> 2, lc = lane & 3;
    const int bx = blockIdx.x, by = blockIdx.y;

    const uint32_t sA_u = (uint32_t)__cvta_generic_to_shared(sA);
    const uint32_t sB_u = (uint32_t)__cvta_generic_to_shared(sB);

    float acc[4][4][4];
    #pragma unroll
    for (int mi = 0; mi < 4; mi++)
        #pragma unroll
        for (int ni = 0; ni < 4; ni++)
            #pragma unroll
            for (int r = 0; r < 4; r++) acc[mi][ni][r] = 0.f;

    const int nstage = K / 32;

    // stage loader
    auto load_stage = [&](int p, int st) {
        const int k0 = st * 32;
        const float* Ag = A + (size_t)(by * 128) * K + k0;
        #pragma unroll
        for (int i = 0; i < 4; i++) {
            int idx = tid + i * 256;            // 0..1023 float4s
            int r = idx >> 3, c = (idx & 7) * 4;
            uint32_t d = sA_u + (uint32_t)((p * GA_FLOATS + r * GA_STRIDE + c) * 4);
            CP_ASYNC_CG(d, Ag + (size_t)r * K + c);
        }
        const float* Bg = B + (size_t)k0 * N + bx * 128;
        #pragma unroll
        for (int i = 0; i < 4; i++) {
            int idx = tid + i * 256;
            int kr = idx >> 5, c = (idx & 31) * 4;
            uint32_t d = sB_u + (uint32_t)((p * GB_FLOATS + kr * GB_STRIDE + c) * 4);
            CP_ASYNC_CG(d, Bg + (size_t)kr * N + c);
        }
    };

    load_stage(0, 0);
    CP_COMMIT();

    for (int st = 0; st < nstage; st++) {
        if (st + 1 < nstage) load_stage((st + 1) & 1, st + 1);
        CP_COMMIT();
        CP_WAIT1();            // current stage resident
        __syncthreads();

        const float* cA = sA + (st & 1) * GA_FLOATS;
        const float* cB = sB + (st & 1) * GB_FLOATS;

        #pragma unroll
        for (int kc = 0; kc < 4; kc++) {
            const int k0 = kc * 8;
            uint32_t a[4][4];
            #pragma unroll
            for (int mi = 0; mi < 4; mi++) {
                int row0 = wm * 64 + mi * 16 + lr;
                a[mi][0] = __float_as_uint(cA[row0 * GA_STRIDE + k0 + lc]);
                a[mi][1] = __float_as_uint(cA[(row0 + 8) * GA_STRIDE + k0 + lc]);
                a[mi][2] = __float_as_uint(cA[row0 * GA_STRIDE + k0 + lc + 4]);
                a[mi][3] = __float_as_uint(cA[(row0 + 8) * GA_STRIDE + k0 + lc + 4]);
            }
            uint32_t b[4][2];
            #pragma unroll
            for (int ni = 0; ni < 4; ni++) {
                int col = wn * 32 + ni * 8 + lr;
                b[ni][0] = __float_as_uint(cB[(k0 + lc) * GB_STRIDE + col]);
                b[ni][1] = __float_as_uint(cB[(k0 + lc + 4) * GB_STRIDE + col]);
            }
            #pragma unroll
            for (int mi = 0; mi < 4; mi++)
                #pragma unroll
                for (int ni = 0; ni < 4; ni++)
                    mma_tf32(acc[mi][ni], a[mi], b[ni]);
        }
        __syncthreads();
    }

    // Epilogue
    #pragma unroll
    for (int mi = 0; mi < 4; mi++) {
        #pragma unroll
        for (int ni = 0; ni < 4; ni++) {
            int row = by * 128 + wm * 64 + mi * 16 + lr;
            int col = bx * 128 + wn * 32 + ni * 8 + lc * 2;
            float2 v0 = make_float2(acc[mi][ni][0], acc[mi][ni][1]);
            float2 v1 = make_float2(acc[mi][ni][2], acc[mi][ni][3]);
            *(float2*)(C + (size_t)row * N + col) = v0;
            *(float2*)(C + (size_t)(row + 8) * N + col) = v1;
        }
    }
}

// ---------------------------------------------------------------------------
// Flash attention (fp32, causal, GQA) — unchanged from R2 except the epilogue
// rounds O to tf32 so the Wo GEMM operand is already rounded.
// ---------------------------------------------------------------------------
#define FA_SQT  (128 * 68)
#define FA_SKT  (128 * 68)
#define FA_SV   (64 * 128)
#define FA_SP   (64 * 68)
#define FA_SMEM_FLOATS (FA_SQT + FA_SKT + FA_SV + FA_SP)

__global__ __launch_bounds__(256) void flash_kernel(
    const float* __restrict__ Q, const float* __restrict__ K,
    const float* __restrict__ V, float* __restrict__ O)
{
    extern __shared__ float smem[];
    float* sQt = smem;
    float* sKt = sQt + FA_SQT;
    float* sV  = sKt + FA_SKT;
    float* sP  = sV + FA_SV;

    const int qt = blockIdx.x, h = blockIdx.y, b = blockIdx.z;
    const int kvh = h / NREPv;
    const int tid = threadIdx.x;
    const int tx = tid & 15, ty = tid >> 4;

    {
        int r = tid >> 2, c0 = (tid & 3) * 32;
        const float* qp = Q + ((size_t)(b * Nv + qt * 64 + r) * Hv + h) * HDv + c0;
        #pragma unroll
        for (int i = 0; i < 8; i++) {
            float4 v = *(const float4*)(qp + i * 4);
            int d = c0 + i * 4;
            sQt[(d + 0) * 68 + r] = v.x;
            sQt[(d + 1) * 68 + r] = v.y;
            sQt[(d + 2) * 68 + r] = v.z;
            sQt[(d + 3) * 68 + r] = v.w;
        }
    }

    float mrow[4], lrow[4], o[4][8];
    #pragma unroll
    for (int i = 0; i < 4; i++) {
        mrow[i] = -1e30f; lrow[i] = 0.f;
        #pragma unroll
        for (int c = 0; c < 8; c++) o[i][c] = 0.f;
    }

    const float scale = 0.08838834764831845f;

    for (int kt = 0; kt <= qt; kt++) {
        {
            int r = tid >> 2, c0 = (tid & 3) * 32;
            const float* kp = K + ((size_t)(b * Nv + kt * 64 + r) * KVHv + kvh) * HDv + c0;
            const float* vp = V + ((size_t)(b * Nv + kt * 64 + r) * KVHv + kvh) * HDv + c0;
            #pragma unroll
            for (int i = 0; i < 8; i++) {
                float4 kv = *(const float4*)(kp + i * 4);
                int d = c0 + i * 4;
                sKt[(d + 0) * 68 + r] = kv.x;
                sKt[(d + 1) * 68 + r] = kv.y;
                sKt[(d + 2) * 68 + r] = kv.z;
                sKt[(d + 3) * 68 + r] = kv.w;
                *(float4*)&sV[r * 128 + d] = *(const float4*)(vp + i * 4);
            }
        }
        __syncthreads();

        float s[4][4];
        #pragma unroll
        for (int i = 0; i < 4; i++)
            #pragma unroll
            for (int j = 0; j < 4; j++) s[i][j] = 0.f;

        #pragma unroll 4
        for (int d = 0; d < 128; d++) {
            float a[4], bb[4];
            *(float4*)a  = *(const float4*)&sQt[d * 68 + ty * 4];
            *(float4*)bb = *(const float4*)&sKt[d * 68 + tx * 4];
            #pragma unroll
            for (int i = 0; i < 4; i++)
                #pragma unroll
                for (int j = 0; j < 4; j++)
                    s[i][j] += a[i] * bb[j];
        }

        const bool diag = (kt == qt);
        #pragma unroll
        for (int i = 0; i < 4; i++)
            #pragma unroll
            for (int j = 0; j < 4; j++) {
                float val = s[i][j] * scale;
                if (diag && (tx * 4 + j) > (ty * 4 + i)) val = -1e30f;
                s[i][j] = val;
            }

        #pragma unroll
        for (int i = 0; i < 4; i++) {
            float mt = fmaxf(fmaxf(s[i][0], s[i][1]), fmaxf(s[i][2], s[i][3]));
            #pragma unroll
            for (int off = 8; off >= 1; off >>= 1)
                mt = fmaxf(mt, __shfl_xor_sync(0xffffffffu, mt, off));
            float mnew  = fmaxf(mrow[i], mt);
            float alpha = __expf(mrow[i] - mnew);
            float rs = 0.f;
            #pragma unroll
            for (int j = 0; j < 4; j++) {
                float p = __expf(s[i][j] - mnew);
                s[i][j] = p; rs += p;
            }
            #pragma unroll
            for (int off = 8; off >= 1; off >>= 1)
                rs += __shfl_xor_sync(0xffffffffu, rs, off);
            lrow[i] = lrow[i] * alpha + rs;
            mrow[i] = mnew;
            #pragma unroll
            for (int c = 0; c < 8; c++) o[i][c] *= alpha;
            float4 pv = make_float4(s[i][0], s[i][1], s[i][2], s[i][3]);
            *(float4*)&sP[(ty * 4 + i) * 68 + tx * 4] = pv;
        }
        __syncthreads();

        #pragma unroll 4
        for (int j = 0; j < 64; j++) {
            float a0 = sP[(ty * 4 + 0) * 68 + j];
            float a1 = sP[(ty * 4 + 1) * 68 + j];
            float a2 = sP[(ty * 4 + 2) * 68 + j];
            float a3 = sP[(ty * 4 + 3) * 68 + j];
            float bb[8];
            *(float4*)&bb[0] = *(const float4*)&sV[j * 128 + tx * 4];
            *(float4*)&bb[4] = *(const float4*)&sV[j * 128 + 64 + tx * 4];
            #pragma unroll
            for (int c = 0; c < 8; c++) {
                o[0][c] += a0 * bb[c];
                o[1][c] += a1 * bb[c];
                o[2][c] += a2 * bb[c];
                o[3][c] += a3 * bb[c];
            }
        }
        __syncthreads();
    }

    #pragma unroll
    for (int i = 0; i < 4; i++) {
        float inv = 1.f / lrow[i];
        int row = qt * 64 + ty * 4 + i;
        float* op = O + ((size_t)(b * Nv + row) * Hv + h) * HDv;
        float4 v0 = make_float4(f2tf32(o[i][0] * inv), f2tf32(o[i][1] * inv),
                                f2tf32(o[i][2] * inv), f2tf32(o[i][3] * inv));
        float4 v1 = make_float4(f2tf32(o[i][4] * inv), f2tf32(o[i][5] * inv),
                                f2tf32(o[i][6] * inv), f2tf32(o[i][7] * inv));
        *(float4*)(op + tx * 4)      = v0;
        *(float4*)(op + 64 + tx * 4) = v1;
    }
}

// ---------------------------------------------------------------------------
// Launch
// ---------------------------------------------------------------------------
extern "C" void kernel_launch(void* const* d_in, const int* in_sizes, int n_in,
                              void* d_out, int out_size)
{
    const float* x  = (const float*)d_in[0];
    const float* Wq = (const float*)d_in[2];
    const float* Wk = (const float*)d_in[3];
    const float* Wv = (const float*)d_in[4];
    const float* Wo = (const float*)d_in[5];
    float* out = (float*)d_out;

    float *qb, *kb, *vb, *ob, *xr, *wqr, *wkr, *wvr, *wor;
    cudaGetSymbolAddress((void**)&qb, g_Q);
    cudaGetSymbolAddress((void**)&kb, g_K);
    cudaGetSymbolAddress((void**)&vb, g_V);
    cudaGetSymbolAddress((void**)&ob, g_O);
    cudaGetSymbolAddress((void**)&xr, g_xr);
    cudaGetSymbolAddress((void**)&wqr, g_Wqr);
    cudaGetSymbolAddress((void**)&wkr, g_Wkr);
    cudaGetSymbolAddress((void**)&wvr, g_Wvr);
    cudaGetSymbolAddress((void**)&wor, g_Wor);

    const int M = Bv * Nv;  // 4096
    dim3 blk(256);

    // Round operands to tf32-representable fp32
    auto roundn = [&](const float* s, float* d, size_t n) {
        int n4 = (int)(n / 4);
        round_tf32_kernel<<<(n4 + 255) / 256, 256>>>((const float4*)s, (float4*)d, n4);
    };
    roundn(x,  xr,  (size_t)M * DIMv);
    roundn(Wq, wqr, (size_t)DIMv * Hv * HDv);
    roundn(Wk, wkr, (size_t)DIMv * KVHv * HDv);
    roundn(Wv, wvr, (size_t)DIMv * KVHv * HDv);
    roundn(Wo, wor, (size_t)Hv * HDv * DIMv);

    cudaFuncSetAttribute(gemm_tf32_kernel, cudaFuncAttributeMaxDynamicSharedMemorySize,
                         GEMM_SMEM_BYTES);

    // Projections (tensor cores)
    gemm_tf32_kernel<<<dim3((Hv * HDv) / 128, M / 128), blk, GEMM_SMEM_BYTES>>>(
        xr, wqr, qb, M, Hv * HDv, DIMv);
    gemm_tf32_kernel<<<dim3((KVHv * HDv) / 128, M / 128), blk, GEMM_SMEM_BYTES>>>(
        xr, wkr, kb, M, KVHv * HDv, DIMv);
    gemm_tf32_kernel<<<dim3((KVHv * HDv) / 128, M / 128), blk, GEMM_SMEM_BYTES>>>(
        xr, wvr, vb, M, KVHv * HDv, DIMv);

    // Attention (fp32)
    const size_t fa_smem = (size_t)FA_SMEM_FLOATS * sizeof(float);
    cudaFuncSetAttribute(flash_kernel, cudaFuncAttributeMaxDynamicSharedMemorySize,
                         (int)fa_smem);
    flash_kernel<<<dim3(Nv / 64, Hv, Bv), blk, fa_smem>>>(qb, kb, vb, ob);

    // Output projection (tensor cores)
    gemm_tf32_kernel<<<dim3(DIMv / 128, M / 128), blk, GEMM_SMEM_BYTES>>>(
        ob, wor, out, M, DIMv, DIMv);
}